// round 1
// baseline (speedup 1.0000x reference)
#include <cuda_runtime.h>

// ---------------------------------------------------------------------------
// EngramModule: fused engram forward.
//   Stage 1 (precompute): per-slot projection tables
//       V[s][d]  = sum_e emb[s][e] * val_W[d][64*g+e]          (16384 x 128)
//       K[s][c]  = sum_e emb[s][e] * key_W[c/128][c%128][64*g+e] (16384 x 512)
//     where g = s >> 12 (which of the 4 ngram/head groups the slot belongs to)
//   Stage 2 (main): per-token hash -> table gather -> gates -> rmsnorms ->
//     fused depthwise conv (K=4) + silu + residual, chunked over T with a
//     3-token recompute halo. No intermediate DRAM tensors.
// ---------------------------------------------------------------------------

#define Bq   8
#define Tq   4096
#define CHq  512          // N_STREAMS * EMBED_DIM
#define S_TOK 32
#define CHUNKS (Tq / S_TOK)   // 128

__device__ float g_Vtab[16384 * 128];   // 8 MB scratch
__device__ float g_Ktab[16384 * 512];   // 32 MB scratch

// ---------------------------------------------------------------------------
// Stage 1: 4 group-GEMMs of (4096 x 64) @ (64 x 640), fp32.
// Tile 64x64 per block, 256 threads, 4x4 micro-tile, k-chunks of 16.
// Shared tiles stored [e][row] so the inner loop uses float4 LDS.
// ---------------------------------------------------------------------------
__global__ void __launch_bounds__(256) precompute_kernel(
    const float* __restrict__ emb,      // (16384, 64)
    const float* __restrict__ valW,     // (128, 256)
    const float* __restrict__ keyW)     // (4, 128, 256) == (512, 256)
{
    __shared__ float As[16][68];
    __shared__ float Bs[16][68];

    const int tid  = threadIdx.x;
    const int g    = blockIdx.z;   // group 0..3
    const int mblk = blockIdx.y;   // slot tile 0..63
    const int nblk = blockIdx.x;   // col tile 0..9 (640 cols: 128 V + 512 K)

    const int row0 = (tid >> 4) << 2;
    const int col0 = (tid & 15) << 2;

    float acc[4][4];
#pragma unroll
    for (int i = 0; i < 4; i++)
#pragma unroll
        for (int j = 0; j < 4; j++) acc[i][j] = 0.f;

    const int ls = tid >> 2;         // 0..63
    const int le = (tid & 3) << 2;   // 0,4,8,12

    const float* erow = emb + (size_t)((g << 12) + (mblk << 6) + ls) * 64;
    const int gcolL = (nblk << 6) + ls;
    const float* wrow = (gcolL < 128) ? (valW + (size_t)gcolL * 256)
                                      : (keyW + (size_t)(gcolL - 128) * 256);
    wrow += g * 64;

#pragma unroll
    for (int kc = 0; kc < 4; kc++) {
        float4 av = *(const float4*)(erow + kc * 16 + le);
        float4 bv = *(const float4*)(wrow + kc * 16 + le);
        As[le + 0][ls] = av.x; As[le + 1][ls] = av.y;
        As[le + 2][ls] = av.z; As[le + 3][ls] = av.w;
        Bs[le + 0][ls] = bv.x; Bs[le + 1][ls] = bv.y;
        Bs[le + 2][ls] = bv.z; Bs[le + 3][ls] = bv.w;
        __syncthreads();
#pragma unroll
        for (int e = 0; e < 16; e++) {
            float4 a = *(const float4*)&As[e][row0];
            float4 b = *(const float4*)&Bs[e][col0];
            acc[0][0] += a.x * b.x; acc[0][1] += a.x * b.y;
            acc[0][2] += a.x * b.z; acc[0][3] += a.x * b.w;
            acc[1][0] += a.y * b.x; acc[1][1] += a.y * b.y;
            acc[1][2] += a.y * b.z; acc[1][3] += a.y * b.w;
            acc[2][0] += a.z * b.x; acc[2][1] += a.z * b.y;
            acc[2][2] += a.z * b.z; acc[2][3] += a.z * b.w;
            acc[3][0] += a.w * b.x; acc[3][1] += a.w * b.y;
            acc[3][2] += a.w * b.z; acc[3][3] += a.w * b.w;
        }
        __syncthreads();
    }

    const int slotBase = (g << 12) + (mblk << 6) + row0;
    const int colBase  = (nblk << 6) + col0;
#pragma unroll
    for (int i = 0; i < 4; i++) {
        const int slot = slotBase + i;
#pragma unroll
        for (int j = 0; j < 4; j++) {
            const int gc = colBase + j;
            if (gc < 128) g_Vtab[slot * 128 + gc]        = acc[i][j];
            else          g_Ktab[slot * 512 + (gc - 128)] = acc[i][j];
        }
    }
}

// ---------------------------------------------------------------------------
// Stage 2: main fused kernel. One block = (b, 32-token chunk), 512 threads
// (thread c = stream*128 + d). Tokens processed sequentially (3-token halo
// for the causal depthwise conv); all reductions fused into one 4-value
// block reduction per token; xn kept in a 4-slot shared ring buffer.
// ---------------------------------------------------------------------------
__global__ void __launch_bounds__(512) engram_main_kernel(
    const float* __restrict__ x,        // (B,T,4,128)
    const int*   __restrict__ ids,      // (B,T)
    const int*   __restrict__ mult,     // (2,2,3)
    const float* __restrict__ key_b,    // (4,128)
    const float* __restrict__ val_b,    // (128)
    const float* __restrict__ wq,       // (4,128)
    const float* __restrict__ wk,       // (4,128)
    const float* __restrict__ convw,    // (512,1,4)
    const float* __restrict__ convn,    // (4,128)
    float*       __restrict__ out)      // (B,T,4,128)
{
    const int c      = threadIdx.x;       // 0..511
    const int d      = c & 127;
    const int lane   = c & 31;
    const int stream = c >> 7;
    const int wis    = (c >> 5) & 3;      // warp index within stream group

    const int b     = blockIdx.x >> 7;    // CHUNKS = 128
    const int chunk = blockIdx.x & 127;
    const int t0    = chunk * S_TOK;

    __shared__ float  s_xn[4][CHq];       // xn ring buffer (4 tokens)
    __shared__ float4 s_part[4][4];       // [stream][warp-in-stream] partials
    __shared__ int    s_ids[S_TOK + 5];

    // token ids for t0-5 .. t0+S_TOK-1 (hash window needs t-2..t)
    for (int i = c; i < S_TOK + 5; i += 512) {
        const int t = t0 - 5 + i;
        s_ids[i] = (t >= 0) ? ids[b * Tq + t] : 0;
    }
#pragma unroll
    for (int r = 0; r < 4; r++) s_xn[r][c] = 0.f;

    // loop-invariant per-channel parameters
    const float kb   = key_b[c];
    const float vbb  = val_b[d];
    const float wqk  = wq[c] * wk[c];
    const float cw0  = convw[c * 4 + 0];
    const float cw1  = convw[c * 4 + 1];
    const float cw2  = convw[c * 4 + 2];
    const float cw3  = convw[c * 4 + 3];
    const float cvn  = convn[c];
    // hash multipliers (products stay < 2^29, XOR < 2^29, so nonneg; %4096 == &4095)
    const int m00 = mult[0],  m01 = mult[1];
    const int m10 = mult[3],  m11 = mult[4];
    const int m20 = mult[6],  m21 = mult[7],  m22 = mult[8];
    const int m30 = mult[9],  m31 = mult[10], m32 = mult[11];

    const float inv128     = 0.0078125f;
    const float eps        = 1.1920929e-7f;
    const float invsqrt128 = 0.08838834764831845f;

    __syncthreads();

    for (int tt = 0; tt < S_TOK + 3; tt++) {
        const int t = t0 - 3 + tt;
        const bool active = (t >= 0);     // block-uniform
        float vb = 0.f;

        if (active) {
            const int ia = s_ids[tt], ib = s_ids[tt + 1], ic = s_ids[tt + 2];
            const int h0 = ((ib * m00) ^ (ic * m01)) & 4095;
            const int h1 = (((ib * m10) ^ (ic * m11)) & 4095) + 4096;
            const int h2 = (((ia * m20) ^ (ib * m21) ^ (ic * m22)) & 4095) + 8192;
            const int h3 = (((ia * m30) ^ (ib * m31) ^ (ic * m32)) & 4095) + 12288;

            const float kr = g_Ktab[h0 * 512 + c] + g_Ktab[h1 * 512 + c]
                           + g_Ktab[h2 * 512 + c] + g_Ktab[h3 * 512 + c] + kb;
            vb = g_Vtab[h0 * 128 + d] + g_Vtab[h1 * 128 + d]
               + g_Vtab[h2 * 128 + d] + g_Vtab[h3 * 128 + d] + vbb;
            const float qr = x[(b * Tq + t) * CHq + c];

            float p0 = qr * qr;
            float p1 = kr * kr;
            float p2 = qr * kr * wqk;
            float p3 = vb * vb;
#pragma unroll
            for (int off = 16; off; off >>= 1) {
                p0 += __shfl_xor_sync(0xffffffffu, p0, off);
                p1 += __shfl_xor_sync(0xffffffffu, p1, off);
                p2 += __shfl_xor_sync(0xffffffffu, p2, off);
                p3 += __shfl_xor_sync(0xffffffffu, p3, off);
            }
            if (lane == 0) s_part[stream][wis] = make_float4(p0, p1, p2, p3);
        }
        __syncthreads();

        float vg = 0.f;
        if (active) {
            const float4 a0 = s_part[stream][0];
            const float4 a1 = s_part[stream][1];
            const float4 a2 = s_part[stream][2];
            const float4 a3 = s_part[stream][3];
            const float sq  = a0.x + a1.x + a2.x + a3.x;
            const float sk  = a0.y + a1.y + a2.y + a3.y;
            const float sqk = a0.z + a1.z + a2.z + a3.z;
            const float svb = a0.w + a1.w + a2.w + a3.w;

            const float rsq   = rsqrtf(sq * inv128 + eps);
            const float rsk   = rsqrtf(sk * inv128 + eps);
            const float score = sqk * rsq * rsk * invsqrt128;
            const float gate  = 1.f / (1.f + expf(-score));
            vg = vb * gate;
            const float msq = gate * gate * svb * inv128;
            s_xn[tt & 3][c] = vg * rsqrtf(msq + eps) * cvn;
        }
        __syncthreads();

        if (tt >= 3) {
            float y = cw0 * s_xn[(tt - 3) & 3][c]
                    + cw1 * s_xn[(tt - 2) & 3][c]
                    + cw2 * s_xn[(tt - 1) & 3][c]
                    + cw3 * s_xn[tt & 3][c];
            y = y / (1.f + expf(-y));   // silu
            out[(b * Tq + t) * CHq + c] = vg + y;
        }
        // next iteration's first __syncthreads() orders these ring reads
        // before the ring slot is overwritten.
    }
}

// ---------------------------------------------------------------------------
// Launch. Input order per metadata: x, input_ids, multipliers, embedding,
// val_W, val_b, key_W, key_b, normq_w, normk_w, conv_w, convnorm_w.
// ---------------------------------------------------------------------------
extern "C" void kernel_launch(void* const* d_in, const int* in_sizes, int n_in,
                              void* d_out, int out_size)
{
    const float* x          = (const float*)d_in[0];
    const int*   input_ids  = (const int*)  d_in[1];
    const int*   multipliers= (const int*)  d_in[2];
    const float* embedding  = (const float*)d_in[3];
    const float* val_W      = (const float*)d_in[4];
    const float* val_b      = (const float*)d_in[5];
    const float* key_W      = (const float*)d_in[6];
    const float* key_b      = (const float*)d_in[7];
    const float* normq_w    = (const float*)d_in[8];
    const float* normk_w    = (const float*)d_in[9];
    const float* conv_w     = (const float*)d_in[10];
    const float* convnorm_w = (const float*)d_in[11];
    float* out = (float*)d_out;

    dim3 gp(10, 64, 4);
    precompute_kernel<<<gp, 256>>>(embedding, val_W, key_W);

    engram_main_kernel<<<Bq * CHUNKS, 512>>>(
        x, input_ids, multipliers, key_b, val_b,
        normq_w, normk_w, conv_w, convnorm_w, out);
}

// round 2
// speedup vs baseline: 1.4451x; 1.4451x over previous
#include <cuda_runtime.h>

// ---------------------------------------------------------------------------
// EngramModule fused forward.
// Stage 1: per-slot projection tables (group GEMMs), biases/4 folded in.
// Stage 2: warp-per-(token-run, stream) fused kernel — no __syncthreads,
//          warp-shuffle reductions, conv history in registers.
// ---------------------------------------------------------------------------

#define Bq    8
#define Tq    4096
#define CHq   512          // N_STREAMS * EMBED_DIM
#define R_TOK 32
#define CHUNKS (Tq / R_TOK)   // 128

__device__ float g_Vtab[16384 * 128];   // 8 MB
__device__ float g_Ktab[16384 * 512];   // 32 MB

// ---------------------------------------------------------------------------
// Stage 1: 4 group-GEMMs of (4096 x 64) @ (64 x 640), fp32.
// ---------------------------------------------------------------------------
__global__ void __launch_bounds__(256) precompute_kernel(
    const float* __restrict__ emb,      // (16384, 64)
    const float* __restrict__ valW,     // (128, 256)
    const float* __restrict__ keyW,     // (512, 256)
    const float* __restrict__ valb,     // (128)
    const float* __restrict__ keyb)     // (512)
{
    __shared__ float As[16][68];
    __shared__ float Bs[16][68];

    const int tid  = threadIdx.x;
    const int g    = blockIdx.z;
    const int mblk = blockIdx.y;
    const int nblk = blockIdx.x;

    const int row0 = (tid >> 4) << 2;
    const int col0 = (tid & 15) << 2;

    float acc[4][4];
#pragma unroll
    for (int i = 0; i < 4; i++)
#pragma unroll
        for (int j = 0; j < 4; j++) acc[i][j] = 0.f;

    const int ls = tid >> 2;
    const int le = (tid & 3) << 2;

    const float* erow = emb + (size_t)((g << 12) + (mblk << 6) + ls) * 64;
    const int gcolL = (nblk << 6) + ls;
    const float* wrow = (gcolL < 128) ? (valW + (size_t)gcolL * 256)
                                      : (keyW + (size_t)(gcolL - 128) * 256);
    wrow += g * 64;

#pragma unroll
    for (int kc = 0; kc < 4; kc++) {
        float4 av = *(const float4*)(erow + kc * 16 + le);
        float4 bv = *(const float4*)(wrow + kc * 16 + le);
        As[le + 0][ls] = av.x; As[le + 1][ls] = av.y;
        As[le + 2][ls] = av.z; As[le + 3][ls] = av.w;
        Bs[le + 0][ls] = bv.x; Bs[le + 1][ls] = bv.y;
        Bs[le + 2][ls] = bv.z; Bs[le + 3][ls] = bv.w;
        __syncthreads();
#pragma unroll
        for (int e = 0; e < 16; e++) {
            float4 a = *(const float4*)&As[e][row0];
            float4 b = *(const float4*)&Bs[e][col0];
            acc[0][0] += a.x * b.x; acc[0][1] += a.x * b.y;
            acc[0][2] += a.x * b.z; acc[0][3] += a.x * b.w;
            acc[1][0] += a.y * b.x; acc[1][1] += a.y * b.y;
            acc[1][2] += a.y * b.z; acc[1][3] += a.y * b.w;
            acc[2][0] += a.z * b.x; acc[2][1] += a.z * b.y;
            acc[2][2] += a.z * b.z; acc[2][3] += a.z * b.w;
            acc[3][0] += a.w * b.x; acc[3][1] += a.w * b.y;
            acc[3][2] += a.w * b.z; acc[3][3] += a.w * b.w;
        }
        __syncthreads();
    }

    const int slotBase = (g << 12) + (mblk << 6) + row0;
    const int colBase  = (nblk << 6) + col0;
#pragma unroll
    for (int i = 0; i < 4; i++) {
        const int slot = slotBase + i;
#pragma unroll
        for (int j = 0; j < 4; j++) {
            const int gc = colBase + j;
            if (gc < 128)
                g_Vtab[slot * 128 + gc] = acc[i][j] + 0.25f * valb[gc];
            else
                g_Ktab[slot * 512 + (gc - 128)] = acc[i][j] + 0.25f * keyb[gc - 128];
        }
    }
}

// ---------------------------------------------------------------------------
// Stage 2: warp = (32-token run, stream); lane = 4 consecutive channels.
// No block barriers. Conv history kept in rotating float4 registers.
// Block = 256 threads = 2 chunks x 4 streams (V-row reads shared via L1).
// ---------------------------------------------------------------------------
__global__ void __launch_bounds__(256) engram_main_kernel(
    const float* __restrict__ x,        // (B,T,4,128)
    const int*   __restrict__ ids,      // (B,T)
    const int*   __restrict__ mult,     // (2,2,3)
    const float* __restrict__ wq,       // (4,128)
    const float* __restrict__ wk,       // (4,128)
    const float* __restrict__ convw,    // (512,4)
    const float* __restrict__ convn,    // (4,128)
    float*       __restrict__ out)      // (B,T,4,128)
{
    const int w      = threadIdx.x >> 5;
    const int lane   = threadIdx.x & 31;
    const int stream = w & 3;
    const int b      = blockIdx.x >> 6;
    const int chunk  = ((blockIdx.x & 63) << 1) + (w >> 2);
    const int t0     = chunk * R_TOK;

    const int c = stream * 128 + lane * 4;   // base channel
    const int d = lane * 4;                  // base dim for V

    // loop-invariant per-thread parameters
    const float4 wq4  = *(const float4*)(wq + c);
    const float4 wk4  = *(const float4*)(wk + c);
    const float4 wqk4 = make_float4(wq4.x * wk4.x, wq4.y * wk4.y,
                                    wq4.z * wk4.z, wq4.w * wk4.w);
    const float4 cvn4 = *(const float4*)(convn + c);
    const float4 cwA  = *(const float4*)(convw + (c + 0) * 4);  // taps ch c+0
    const float4 cwB  = *(const float4*)(convw + (c + 1) * 4);
    const float4 cwC  = *(const float4*)(convw + (c + 2) * 4);
    const float4 cwD  = *(const float4*)(convw + (c + 3) * 4);

    const int m00 = mult[0],  m01 = mult[1];
    const int m10 = mult[3],  m11 = mult[4];
    const int m20 = mult[6],  m21 = mult[7],  m22 = mult[8];
    const int m30 = mult[9],  m31 = mult[10], m32 = mult[11];

    const float inv128     = 0.0078125f;
    const float eps        = 1.1920929e-7f;
    const float invsqrt128 = 0.08838834764831845f;

    const int   idBase = b * Tq;
    const float* xBase = x   + (size_t)idBase * CHq + c;
    float*       oBase = out + (size_t)idBase * CHq + c;

    float4 h1 = make_float4(0.f, 0.f, 0.f, 0.f);   // xn(t-1)
    float4 h2 = h1;                                 // xn(t-2)
    float4 h3 = h1;                                 // xn(t-3)

    for (int tt = -3; tt < R_TOK; tt++) {
        const int t = t0 + tt;
        if (t < 0) continue;                        // warp-uniform

        const int ic = __ldg(ids + idBase + t);
        const int ib = (t >= 1) ? __ldg(ids + idBase + t - 1) : 0;
        const int ia = (t >= 2) ? __ldg(ids + idBase + t - 2) : 0;

        const int h0i = (((ib * m00) ^ (ic * m01)) & 4095);
        const int h1i = (((ib * m10) ^ (ic * m11)) & 4095) + 4096;
        const int h2i = (((ia * m20) ^ (ib * m21) ^ (ic * m22)) & 4095) + 8192;
        const int h3i = (((ia * m30) ^ (ib * m31) ^ (ic * m32)) & 4095) + 12288;

        const float4 k0 = *(const float4*)(g_Ktab + (size_t)h0i * 512 + c);
        const float4 k1 = *(const float4*)(g_Ktab + (size_t)h1i * 512 + c);
        const float4 k2 = *(const float4*)(g_Ktab + (size_t)h2i * 512 + c);
        const float4 k3 = *(const float4*)(g_Ktab + (size_t)h3i * 512 + c);
        const float4 v0 = *(const float4*)(g_Vtab + (size_t)h0i * 128 + d);
        const float4 v1 = *(const float4*)(g_Vtab + (size_t)h1i * 128 + d);
        const float4 v2 = *(const float4*)(g_Vtab + (size_t)h2i * 128 + d);
        const float4 v3 = *(const float4*)(g_Vtab + (size_t)h3i * 128 + d);

        float4 kr, vb;
        kr.x = k0.x + k1.x + k2.x + k3.x;  kr.y = k0.y + k1.y + k2.y + k3.y;
        kr.z = k0.z + k1.z + k2.z + k3.z;  kr.w = k0.w + k1.w + k2.w + k3.w;
        vb.x = v0.x + v1.x + v2.x + v3.x;  vb.y = v0.y + v1.y + v2.y + v3.y;
        vb.z = v0.z + v1.z + v2.z + v3.z;  vb.w = v0.w + v1.w + v2.w + v3.w;

        const float4 qr = *(const float4*)(xBase + (size_t)t * CHq);

        float p0 = qr.x * qr.x + qr.y * qr.y + qr.z * qr.z + qr.w * qr.w;
        float p1 = kr.x * kr.x + kr.y * kr.y + kr.z * kr.z + kr.w * kr.w;
        float p2 = qr.x * kr.x * wqk4.x + qr.y * kr.y * wqk4.y
                 + qr.z * kr.z * wqk4.z + qr.w * kr.w * wqk4.w;
        float p3 = vb.x * vb.x + vb.y * vb.y + vb.z * vb.z + vb.w * vb.w;

#pragma unroll
        for (int off = 16; off; off >>= 1) {
            p0 += __shfl_xor_sync(0xffffffffu, p0, off);
            p1 += __shfl_xor_sync(0xffffffffu, p1, off);
            p2 += __shfl_xor_sync(0xffffffffu, p2, off);
            p3 += __shfl_xor_sync(0xffffffffu, p3, off);
        }

        const float rsq   = rsqrtf(p0 * inv128 + eps);
        const float rsk   = rsqrtf(p1 * inv128 + eps);
        const float score = p2 * rsq * rsk * invsqrt128;
        const float gate  = 1.f / (1.f + expf(-score));
        const float rr    = rsqrtf(gate * gate * p3 * inv128 + eps) * gate;

        float4 vg, xn;
        vg.x = vb.x * gate;  vg.y = vb.y * gate;
        vg.z = vb.z * gate;  vg.w = vb.w * gate;
        xn.x = vb.x * rr * cvn4.x;  xn.y = vb.y * rr * cvn4.y;
        xn.z = vb.z * rr * cvn4.z;  xn.w = vb.w * rr * cvn4.w;

        if (tt >= 0) {
            float4 y;
            y.x = cwA.x * h3.x + cwA.y * h2.x + cwA.z * h1.x + cwA.w * xn.x;
            y.y = cwB.x * h3.y + cwB.y * h2.y + cwB.z * h1.y + cwB.w * xn.y;
            y.z = cwC.x * h3.z + cwC.y * h2.z + cwC.z * h1.z + cwC.w * xn.z;
            y.w = cwD.x * h3.w + cwD.y * h2.w + cwD.z * h1.w + cwD.w * xn.w;
            y.x = y.x / (1.f + expf(-y.x));
            y.y = y.y / (1.f + expf(-y.y));
            y.z = y.z / (1.f + expf(-y.z));
            y.w = y.w / (1.f + expf(-y.w));
            float4 o;
            o.x = vg.x + y.x;  o.y = vg.y + y.y;
            o.z = vg.z + y.z;  o.w = vg.w + y.w;
            *(float4*)(oBase + (size_t)t * CHq) = o;
        }
        h3 = h2; h2 = h1; h1 = xn;
    }
}

// ---------------------------------------------------------------------------
extern "C" void kernel_launch(void* const* d_in, const int* in_sizes, int n_in,
                              void* d_out, int out_size)
{
    const float* x          = (const float*)d_in[0];
    const int*   input_ids  = (const int*)  d_in[1];
    const int*   multipliers= (const int*)  d_in[2];
    const float* embedding  = (const float*)d_in[3];
    const float* val_W      = (const float*)d_in[4];
    const float* val_b      = (const float*)d_in[5];
    const float* key_W      = (const float*)d_in[6];
    const float* key_b      = (const float*)d_in[7];
    const float* normq_w    = (const float*)d_in[8];
    const float* normk_w    = (const float*)d_in[9];
    const float* conv_w     = (const float*)d_in[10];
    const float* convnorm_w = (const float*)d_in[11];
    float* out = (float*)d_out;

    dim3 gp(10, 64, 4);
    precompute_kernel<<<gp, 256>>>(embedding, val_W, key_W, val_b, key_b);

    engram_main_kernel<<<Bq * (CHUNKS / 2), 256>>>(
        x, input_ids, multipliers,
        normq_w, normk_w, conv_w, convnorm_w, out);
}

// round 3
// speedup vs baseline: 1.5030x; 1.0401x over previous
#include <cuda_runtime.h>

// ---------------------------------------------------------------------------
// EngramModule fused forward.
// Stage 1: per-slot projection tables (group GEMMs), biases/4 folded in.
// Stage 2: warp-per-(token-run, stream), no barriers, fast-math scalar tail,
//          14-shuffle fused reduction, register-carried ids, conv in regs.
// ---------------------------------------------------------------------------

#define Bq    8
#define Tq    4096
#define CHq   512
#define R_TOK 32
#define CHUNKS (Tq / R_TOK)   // 128

__device__ float g_Vtab[16384 * 128];   // 8 MB
__device__ float g_Ktab[16384 * 512];   // 32 MB

// ---------------------------------------------------------------------------
// Stage 1: 4 group-GEMMs of (4096 x 64) @ (64 x 640), fp32. (~76% FFMA peak)
// ---------------------------------------------------------------------------
__global__ void __launch_bounds__(256) precompute_kernel(
    const float* __restrict__ emb,      // (16384, 64)
    const float* __restrict__ valW,     // (128, 256)
    const float* __restrict__ keyW,     // (512, 256)
    const float* __restrict__ valb,     // (128)
    const float* __restrict__ keyb)     // (512)
{
    __shared__ float As[16][68];
    __shared__ float Bs[16][68];

    const int tid  = threadIdx.x;
    const int g    = blockIdx.z;
    const int mblk = blockIdx.y;
    const int nblk = blockIdx.x;

    const int row0 = (tid >> 4) << 2;
    const int col0 = (tid & 15) << 2;

    float acc[4][4];
#pragma unroll
    for (int i = 0; i < 4; i++)
#pragma unroll
        for (int j = 0; j < 4; j++) acc[i][j] = 0.f;

    const int ls = tid >> 2;
    const int le = (tid & 3) << 2;

    const float* erow = emb + (size_t)((g << 12) + (mblk << 6) + ls) * 64;
    const int gcolL = (nblk << 6) + ls;
    const float* wrow = (gcolL < 128) ? (valW + (size_t)gcolL * 256)
                                      : (keyW + (size_t)(gcolL - 128) * 256);
    wrow += g * 64;

#pragma unroll
    for (int kc = 0; kc < 4; kc++) {
        float4 av = *(const float4*)(erow + kc * 16 + le);
        float4 bv = *(const float4*)(wrow + kc * 16 + le);
        As[le + 0][ls] = av.x; As[le + 1][ls] = av.y;
        As[le + 2][ls] = av.z; As[le + 3][ls] = av.w;
        Bs[le + 0][ls] = bv.x; Bs[le + 1][ls] = bv.y;
        Bs[le + 2][ls] = bv.z; Bs[le + 3][ls] = bv.w;
        __syncthreads();
#pragma unroll
        for (int e = 0; e < 16; e++) {
            float4 a = *(const float4*)&As[e][row0];
            float4 b = *(const float4*)&Bs[e][col0];
            acc[0][0] += a.x * b.x; acc[0][1] += a.x * b.y;
            acc[0][2] += a.x * b.z; acc[0][3] += a.x * b.w;
            acc[1][0] += a.y * b.x; acc[1][1] += a.y * b.y;
            acc[1][2] += a.y * b.z; acc[1][3] += a.y * b.w;
            acc[2][0] += a.z * b.x; acc[2][1] += a.z * b.y;
            acc[2][2] += a.z * b.z; acc[2][3] += a.z * b.w;
            acc[3][0] += a.w * b.x; acc[3][1] += a.w * b.y;
            acc[3][2] += a.w * b.z; acc[3][3] += a.w * b.w;
        }
        __syncthreads();
    }

    const int slotBase = (g << 12) + (mblk << 6) + row0;
    const int colBase  = (nblk << 6) + col0;
#pragma unroll
    for (int i = 0; i < 4; i++) {
        const int slot = slotBase + i;
#pragma unroll
        for (int j = 0; j < 4; j++) {
            const int gc = colBase + j;
            if (gc < 128)
                g_Vtab[slot * 128 + gc] = acc[i][j] + 0.25f * valb[gc];
            else
                g_Ktab[slot * 512 + (gc - 128)] = acc[i][j] + 0.25f * keyb[gc - 128];
        }
    }
}

// ---------------------------------------------------------------------------
// Stage 2 main kernel. Block = 128 threads = 4 stream-warps of one chunk.
// ---------------------------------------------------------------------------
__global__ void __launch_bounds__(128) engram_main_kernel(
    const float* __restrict__ x,        // (B,T,4,128)
    const int*   __restrict__ ids,      // (B,T)
    const int*   __restrict__ mult,     // (2,2,3)
    const float* __restrict__ wq,       // (4,128)
    const float* __restrict__ wk,       // (4,128)
    const float* __restrict__ convw,    // (512,4)
    const float* __restrict__ convn,    // (4,128)
    float*       __restrict__ out)      // (B,T,4,128)
{
    const int stream = threadIdx.x >> 5;
    const int lane   = threadIdx.x & 31;
    const int b      = blockIdx.x >> 7;
    const int chunk  = blockIdx.x & 127;
    const int t0     = chunk * R_TOK;

    const int c = stream * 128 + lane * 4;   // base channel
    const int d = lane * 4;                  // base dim for V

    const float4 wq4  = *(const float4*)(wq + c);
    const float4 wk4  = *(const float4*)(wk + c);
    const float4 wqk4 = make_float4(wq4.x * wk4.x, wq4.y * wk4.y,
                                    wq4.z * wk4.z, wq4.w * wk4.w);
    const float4 cvn4 = *(const float4*)(convn + c);
    const float4 cwA  = *(const float4*)(convw + (c + 0) * 4);
    const float4 cwB  = *(const float4*)(convw + (c + 1) * 4);
    const float4 cwC  = *(const float4*)(convw + (c + 2) * 4);
    const float4 cwD  = *(const float4*)(convw + (c + 3) * 4);

    const int m00 = mult[0],  m01 = mult[1];
    const int m10 = mult[3],  m11 = mult[4];
    const int m20 = mult[6],  m21 = mult[7],  m22 = mult[8];
    const int m30 = mult[9],  m31 = mult[10], m32 = mult[11];

    const float inv128     = 0.0078125f;
    const float eps        = 1.1920929e-7f;
    const float invsqrt128 = 0.08838834764831845f;

    const int    idBase = b * Tq;
    const float* xBase  = x   + (size_t)idBase * CHq + c;
    float*       oBase  = out + (size_t)idBase * CHq + c;

    float4 h1 = make_float4(0.f, 0.f, 0.f, 0.f);
    float4 h2 = h1;
    float4 h3 = h1;

    // register-carried ids: ia = id(t-2), ib = id(t-1); pad = 0
    int ia = (t0 - 5 >= 0) ? __ldg(ids + idBase + t0 - 5) : 0;
    int ib = (t0 - 4 >= 0) ? __ldg(ids + idBase + t0 - 4) : 0;

    for (int tt = -3; tt < R_TOK; tt++) {
        const int t  = t0 + tt;
        const int ic = (t >= 0) ? __ldg(ids + idBase + t) : 0;

        if (t >= 0) {
            const int h0i = (((ib * m00) ^ (ic * m01)) & 4095);
            const int h1i = (((ib * m10) ^ (ic * m11)) & 4095) + 4096;
            const int h2i = (((ia * m20) ^ (ib * m21) ^ (ic * m22)) & 4095) + 8192;
            const int h3i = (((ia * m30) ^ (ib * m31) ^ (ic * m32)) & 4095) + 12288;

            const float4 k0 = __ldg((const float4*)(g_Ktab + (size_t)h0i * 512 + c));
            const float4 k1 = __ldg((const float4*)(g_Ktab + (size_t)h1i * 512 + c));
            const float4 k2 = __ldg((const float4*)(g_Ktab + (size_t)h2i * 512 + c));
            const float4 k3 = __ldg((const float4*)(g_Ktab + (size_t)h3i * 512 + c));
            const float4 v0 = __ldg((const float4*)(g_Vtab + (size_t)h0i * 128 + d));
            const float4 v1 = __ldg((const float4*)(g_Vtab + (size_t)h1i * 128 + d));
            const float4 v2 = __ldg((const float4*)(g_Vtab + (size_t)h2i * 128 + d));
            const float4 v3 = __ldg((const float4*)(g_Vtab + (size_t)h3i * 128 + d));
            const float4 qr = *(const float4*)(xBase + (size_t)t * CHq);

            float4 kr, vb;
            kr.x = (k0.x + k1.x) + (k2.x + k3.x);
            kr.y = (k0.y + k1.y) + (k2.y + k3.y);
            kr.z = (k0.z + k1.z) + (k2.z + k3.z);
            kr.w = (k0.w + k1.w) + (k2.w + k3.w);
            vb.x = (v0.x + v1.x) + (v2.x + v3.x);
            vb.y = (v0.y + v1.y) + (v2.y + v3.y);
            vb.z = (v0.z + v1.z) + (v2.z + v3.z);
            vb.w = (v0.w + v1.w) + (v2.w + v3.w);

            float p0 = qr.x * qr.x + qr.y * qr.y + qr.z * qr.z + qr.w * qr.w;
            float p1 = kr.x * kr.x + kr.y * kr.y + kr.z * kr.z + kr.w * kr.w;
            float p2 = qr.x * kr.x * wqk4.x + qr.y * kr.y * wqk4.y
                     + qr.z * kr.z * wqk4.z + qr.w * kr.w * wqk4.w;
            float p3 = vb.x * vb.x + vb.y * vb.y + vb.z * vb.z + vb.w * vb.w;

            // fused 4-value reduction: fold to 2 values across the 16-boundary,
            // butterfly within halves, then cross-exchange. 14 SHFL total.
            const bool lo = (lane < 16);
            float ea = __shfl_xor_sync(0xffffffffu, p0, 16);
            float eb = __shfl_xor_sync(0xffffffffu, p2, 16);
            float aa = lo ? (p0 + ea) : (p2 + eb);
            float ec = __shfl_xor_sync(0xffffffffu, p1, 16);
            float ed = __shfl_xor_sync(0xffffffffu, p3, 16);
            float bb = lo ? (p1 + ec) : (p3 + ed);
#pragma unroll
            for (int off = 8; off; off >>= 1) {
                aa += __shfl_xor_sync(0xffffffffu, aa, off);
                bb += __shfl_xor_sync(0xffffffffu, bb, off);
            }
            const float a2 = __shfl_xor_sync(0xffffffffu, aa, 16);
            const float b2 = __shfl_xor_sync(0xffffffffu, bb, 16);
            const float sq  = lo ? aa : a2;
            const float sk  = lo ? bb : b2;
            const float sqk = lo ? a2 : aa;
            const float svb = lo ? b2 : bb;

            const float rsq   = rsqrtf(sq * inv128 + eps);
            const float rsk   = rsqrtf(sk * inv128 + eps);
            const float score = sqk * rsq * rsk * invsqrt128;
            const float gate  = __fdividef(1.f, 1.f + __expf(-score));
            const float rr    = rsqrtf(gate * gate * svb * inv128 + eps) * gate;

            float4 vg, xn;
            vg.x = vb.x * gate;  vg.y = vb.y * gate;
            vg.z = vb.z * gate;  vg.w = vb.w * gate;
            xn.x = vb.x * rr * cvn4.x;  xn.y = vb.y * rr * cvn4.y;
            xn.z = vb.z * rr * cvn4.z;  xn.w = vb.w * rr * cvn4.w;

            if (tt >= 0) {
                float4 y;
                y.x = cwA.x * h3.x + cwA.y * h2.x + cwA.z * h1.x + cwA.w * xn.x;
                y.y = cwB.x * h3.y + cwB.y * h2.y + cwB.z * h1.y + cwB.w * xn.y;
                y.z = cwC.x * h3.z + cwC.y * h2.z + cwC.z * h1.z + cwC.w * xn.z;
                y.w = cwD.x * h3.w + cwD.y * h2.w + cwD.z * h1.w + cwD.w * xn.w;
                y.x = __fdividef(y.x, 1.f + __expf(-y.x));
                y.y = __fdividef(y.y, 1.f + __expf(-y.y));
                y.z = __fdividef(y.z, 1.f + __expf(-y.z));
                y.w = __fdividef(y.w, 1.f + __expf(-y.w));
                float4 o;
                o.x = vg.x + y.x;  o.y = vg.y + y.y;
                o.z = vg.z + y.z;  o.w = vg.w + y.w;
                *(float4*)(oBase + (size_t)t * CHq) = o;
            }
            h3 = h2; h2 = h1; h1 = xn;
        }
        ia = ib; ib = ic;
    }
}

// ---------------------------------------------------------------------------
extern "C" void kernel_launch(void* const* d_in, const int* in_sizes, int n_in,
                              void* d_out, int out_size)
{
    const float* x          = (const float*)d_in[0];
    const int*   input_ids  = (const int*)  d_in[1];
    const int*   multipliers= (const int*)  d_in[2];
    const float* embedding  = (const float*)d_in[3];
    const float* val_W      = (const float*)d_in[4];
    const float* val_b      = (const float*)d_in[5];
    const float* key_W      = (const float*)d_in[6];
    const float* key_b      = (const float*)d_in[7];
    const float* normq_w    = (const float*)d_in[8];
    const float* normk_w    = (const float*)d_in[9];
    const float* conv_w     = (const float*)d_in[10];
    const float* convnorm_w = (const float*)d_in[11];
    float* out = (float*)d_out;

    dim3 gp(10, 64, 4);
    precompute_kernel<<<gp, 256>>>(embedding, val_W, key_W, val_b, key_b);

    engram_main_kernel<<<Bq * CHUNKS, 128>>>(
        x, input_ids, multipliers,
        normq_w, normk_w, conv_w, convnorm_w, out);
}

// round 4
// speedup vs baseline: 2.0796x; 1.3836x over previous
#include <cuda_runtime.h>

// ---------------------------------------------------------------------------
// EngramModule fused forward.
// Stage 1: per-slot projection tables (group GEMMs), biases/4 folded in.
// Stage 2: warp-per-(token-run, stream), software-pipelined: token t+1's
//          9 LDG.128 gathers are issued before token t's compute, hiding
//          L2 gather latency behind the shuffle/rsqrt chain.
// ---------------------------------------------------------------------------

#define Bq    8
#define Tq    4096
#define CHq   512
#define R_TOK 32
#define CHUNKS (Tq / R_TOK)   // 128

__device__ float g_Vtab[16384 * 128];   // 8 MB
__device__ float g_Ktab[16384 * 512];   // 32 MB

// ---------------------------------------------------------------------------
// Stage 1: 4 group-GEMMs of (4096 x 64) @ (64 x 640), fp32. (~76% FFMA peak)
// ---------------------------------------------------------------------------
__global__ void __launch_bounds__(256) precompute_kernel(
    const float* __restrict__ emb,      // (16384, 64)
    const float* __restrict__ valW,     // (128, 256)
    const float* __restrict__ keyW,     // (512, 256)
    const float* __restrict__ valb,     // (128)
    const float* __restrict__ keyb)     // (512)
{
    __shared__ float As[16][68];
    __shared__ float Bs[16][68];

    const int tid  = threadIdx.x;
    const int g    = blockIdx.z;
    const int mblk = blockIdx.y;
    const int nblk = blockIdx.x;

    const int row0 = (tid >> 4) << 2;
    const int col0 = (tid & 15) << 2;

    float acc[4][4];
#pragma unroll
    for (int i = 0; i < 4; i++)
#pragma unroll
        for (int j = 0; j < 4; j++) acc[i][j] = 0.f;

    const int ls = tid >> 2;
    const int le = (tid & 3) << 2;

    const float* erow = emb + (size_t)((g << 12) + (mblk << 6) + ls) * 64;
    const int gcolL = (nblk << 6) + ls;
    const float* wrow = (gcolL < 128) ? (valW + (size_t)gcolL * 256)
                                      : (keyW + (size_t)(gcolL - 128) * 256);
    wrow += g * 64;

#pragma unroll
    for (int kc = 0; kc < 4; kc++) {
        float4 av = *(const float4*)(erow + kc * 16 + le);
        float4 bv = *(const float4*)(wrow + kc * 16 + le);
        As[le + 0][ls] = av.x; As[le + 1][ls] = av.y;
        As[le + 2][ls] = av.z; As[le + 3][ls] = av.w;
        Bs[le + 0][ls] = bv.x; Bs[le + 1][ls] = bv.y;
        Bs[le + 2][ls] = bv.z; Bs[le + 3][ls] = bv.w;
        __syncthreads();
#pragma unroll
        for (int e = 0; e < 16; e++) {
            float4 a = *(const float4*)&As[e][row0];
            float4 b = *(const float4*)&Bs[e][col0];
            acc[0][0] += a.x * b.x; acc[0][1] += a.x * b.y;
            acc[0][2] += a.x * b.z; acc[0][3] += a.x * b.w;
            acc[1][0] += a.y * b.x; acc[1][1] += a.y * b.y;
            acc[1][2] += a.y * b.z; acc[1][3] += a.y * b.w;
            acc[2][0] += a.z * b.x; acc[2][1] += a.z * b.y;
            acc[2][2] += a.z * b.z; acc[2][3] += a.z * b.w;
            acc[3][0] += a.w * b.x; acc[3][1] += a.w * b.y;
            acc[3][2] += a.w * b.z; acc[3][3] += a.w * b.w;
        }
        __syncthreads();
    }

    const int slotBase = (g << 12) + (mblk << 6) + row0;
    const int colBase  = (nblk << 6) + col0;
#pragma unroll
    for (int i = 0; i < 4; i++) {
        const int slot = slotBase + i;
#pragma unroll
        for (int j = 0; j < 4; j++) {
            const int gc = colBase + j;
            if (gc < 128)
                g_Vtab[slot * 128 + gc] = acc[i][j] + 0.25f * valb[gc];
            else
                g_Ktab[slot * 512 + (gc - 128)] = acc[i][j] + 0.25f * keyb[gc - 128];
        }
    }
}

// ---------------------------------------------------------------------------
// Stage 2 main kernel. Block = 128 threads = 4 stream-warps of one chunk.
// One-token software pipeline: gather(t+1) issued before compute(t).
// ---------------------------------------------------------------------------
struct Tok {
    float4 k0, k1, k2, k3;
    float4 v0, v1, v2, v3;
    float4 q;
};

__global__ void __launch_bounds__(128, 4) engram_main_kernel(
    const float* __restrict__ x,        // (B,T,4,128)
    const int*   __restrict__ ids,      // (B,T)
    const int*   __restrict__ mult,     // (2,2,3)
    const float* __restrict__ wq,       // (4,128)
    const float* __restrict__ wk,       // (4,128)
    const float* __restrict__ convw,    // (512,4)
    const float* __restrict__ convn,    // (4,128)
    float*       __restrict__ out)      // (B,T,4,128)
{
    const int stream = threadIdx.x >> 5;
    const int lane   = threadIdx.x & 31;
    const int b      = blockIdx.x >> 7;
    const int chunk  = blockIdx.x & 127;
    const int t0     = chunk * R_TOK;

    const int c = stream * 128 + lane * 4;   // base channel
    const int d = lane * 4;                  // base dim for V

    const float4 wq4  = *(const float4*)(wq + c);
    const float4 wk4  = *(const float4*)(wk + c);
    const float4 wqk4 = make_float4(wq4.x * wk4.x, wq4.y * wk4.y,
                                    wq4.z * wk4.z, wq4.w * wk4.w);
    const float4 cvn4 = *(const float4*)(convn + c);
    const float4 cwA  = *(const float4*)(convw + (c + 0) * 4);
    const float4 cwB  = *(const float4*)(convw + (c + 1) * 4);
    const float4 cwC  = *(const float4*)(convw + (c + 2) * 4);
    const float4 cwD  = *(const float4*)(convw + (c + 3) * 4);

    const int m00 = mult[0],  m01 = mult[1];
    const int m10 = mult[3],  m11 = mult[4];
    const int m20 = mult[6],  m21 = mult[7],  m22 = mult[8];
    const int m30 = mult[9],  m31 = mult[10], m32 = mult[11];

    const float inv128     = 0.0078125f;
    const float eps        = 1.1920929e-7f;
    const float invsqrt128 = 0.08838834764831845f;

    const int    idBase = b * Tq;
    const float* xBase  = x   + (size_t)idBase * CHq + c;
    float*       oBase  = out + (size_t)idBase * CHq + c;

    float4 h1 = make_float4(0.f, 0.f, 0.f, 0.f);
    float4 h2 = h1;
    float4 h3 = h1;

    // issue all 9 gathers for token with hash history (ia,ib,ic)
    auto gather = [&](Tok& T, int ia, int ib, int ic, int t) {
        const int h0i = (((ib * m00) ^ (ic * m01)) & 4095);
        const int h1i = (((ib * m10) ^ (ic * m11)) & 4095) + 4096;
        const int h2i = (((ia * m20) ^ (ib * m21) ^ (ic * m22)) & 4095) + 8192;
        const int h3i = (((ia * m30) ^ (ib * m31) ^ (ic * m32)) & 4095) + 12288;
        T.k0 = __ldg((const float4*)(g_Ktab + (size_t)h0i * 512 + c));
        T.k1 = __ldg((const float4*)(g_Ktab + (size_t)h1i * 512 + c));
        T.k2 = __ldg((const float4*)(g_Ktab + (size_t)h2i * 512 + c));
        T.k3 = __ldg((const float4*)(g_Ktab + (size_t)h3i * 512 + c));
        T.v0 = __ldg((const float4*)(g_Vtab + (size_t)h0i * 128 + d));
        T.v1 = __ldg((const float4*)(g_Vtab + (size_t)h1i * 128 + d));
        T.v2 = __ldg((const float4*)(g_Vtab + (size_t)h2i * 128 + d));
        T.v3 = __ldg((const float4*)(g_Vtab + (size_t)h3i * 128 + d));
        T.q  = *(const float4*)(xBase + (size_t)t * CHq);
    };

    // full per-token epilogue: reduce, gate, rmsnorms, conv, (store)
    auto compute = [&](const Tok& T, int t, bool store) {
        float4 kr, vb;
        kr.x = (T.k0.x + T.k1.x) + (T.k2.x + T.k3.x);
        kr.y = (T.k0.y + T.k1.y) + (T.k2.y + T.k3.y);
        kr.z = (T.k0.z + T.k1.z) + (T.k2.z + T.k3.z);
        kr.w = (T.k0.w + T.k1.w) + (T.k2.w + T.k3.w);
        vb.x = (T.v0.x + T.v1.x) + (T.v2.x + T.v3.x);
        vb.y = (T.v0.y + T.v1.y) + (T.v2.y + T.v3.y);
        vb.z = (T.v0.z + T.v1.z) + (T.v2.z + T.v3.z);
        vb.w = (T.v0.w + T.v1.w) + (T.v2.w + T.v3.w);

        float p0 = T.q.x * T.q.x + T.q.y * T.q.y + T.q.z * T.q.z + T.q.w * T.q.w;
        float p1 = kr.x * kr.x + kr.y * kr.y + kr.z * kr.z + kr.w * kr.w;
        float p2 = T.q.x * kr.x * wqk4.x + T.q.y * kr.y * wqk4.y
                 + T.q.z * kr.z * wqk4.z + T.q.w * kr.w * wqk4.w;
        float p3 = vb.x * vb.x + vb.y * vb.y + vb.z * vb.z + vb.w * vb.w;

        // fused 4-value warp reduction (14 SHFL)
        const bool lo = (lane < 16);
        float ea = __shfl_xor_sync(0xffffffffu, p0, 16);
        float eb = __shfl_xor_sync(0xffffffffu, p2, 16);
        float aa = lo ? (p0 + ea) : (p2 + eb);
        float ec = __shfl_xor_sync(0xffffffffu, p1, 16);
        float ed = __shfl_xor_sync(0xffffffffu, p3, 16);
        float bb = lo ? (p1 + ec) : (p3 + ed);
#pragma unroll
        for (int off = 8; off; off >>= 1) {
            aa += __shfl_xor_sync(0xffffffffu, aa, off);
            bb += __shfl_xor_sync(0xffffffffu, bb, off);
        }
        const float a2 = __shfl_xor_sync(0xffffffffu, aa, 16);
        const float b2 = __shfl_xor_sync(0xffffffffu, bb, 16);
        const float sq  = lo ? aa : a2;
        const float sk  = lo ? bb : b2;
        const float sqk = lo ? a2 : aa;
        const float svb = lo ? b2 : bb;

        const float rsq   = rsqrtf(sq * inv128 + eps);
        const float rsk   = rsqrtf(sk * inv128 + eps);
        const float score = sqk * rsq * rsk * invsqrt128;
        const float gate  = __fdividef(1.f, 1.f + __expf(-score));
        const float rr    = rsqrtf(gate * gate * svb * inv128 + eps) * gate;

        float4 xn;
        xn.x = vb.x * rr * cvn4.x;  xn.y = vb.y * rr * cvn4.y;
        xn.z = vb.z * rr * cvn4.z;  xn.w = vb.w * rr * cvn4.w;

        if (store) {
            float4 y;
            y.x = cwA.x * h3.x + cwA.y * h2.x + cwA.z * h1.x + cwA.w * xn.x;
            y.y = cwB.x * h3.y + cwB.y * h2.y + cwB.z * h1.y + cwB.w * xn.y;
            y.z = cwC.x * h3.z + cwC.y * h2.z + cwC.z * h1.z + cwC.w * xn.z;
            y.w = cwD.x * h3.w + cwD.y * h2.w + cwD.z * h1.w + cwD.w * xn.w;
            y.x = __fdividef(y.x, 1.f + __expf(-y.x));
            y.y = __fdividef(y.y, 1.f + __expf(-y.y));
            y.z = __fdividef(y.z, 1.f + __expf(-y.z));
            y.w = __fdividef(y.w, 1.f + __expf(-y.w));
            float4 o;
            o.x = vb.x * gate + y.x;  o.y = vb.y * gate + y.y;
            o.z = vb.z * gate + y.z;  o.w = vb.w * gate + y.w;
            *(float4*)(oBase + (size_t)t * CHq) = o;
        }
        h3 = h2; h2 = h1; h1 = xn;
    };

    // ids: ia = id(t-2), ib = id(t-1), zero-padded
    int ia = (t0 - 5 >= 0) ? __ldg(ids + idBase + t0 - 5) : 0;
    int ib = (t0 - 4 >= 0) ? __ldg(ids + idBase + t0 - 4) : 0;

    // ---- halo prologue: tokens t0-3 .. t0-1 (no store) ----
#pragma unroll
    for (int tt = -3; tt < 0; tt++) {
        const int t  = t0 + tt;
        const int ic = (t >= 0) ? __ldg(ids + idBase + t) : 0;
        if (t >= 0) {
            Tok P;
            gather(P, ia, ib, ic, t);
            compute(P, t, false);
        }
        ia = ib; ib = ic;
    }

    // ---- pipelined main loop: tokens t0 .. t0+31 ----
    int ic = __ldg(ids + idBase + t0);
    Tok cur;
    gather(cur, ia, ib, ic, t0);

    for (int tt = 0; tt < R_TOK; tt++) {
        const int t = t0 + tt;
        Tok nxt;
        int in_ = ic;
        if (tt + 1 < R_TOK) {
            in_ = __ldg(ids + idBase + t + 1);
            gather(nxt, ib, ic, in_, t + 1);   // issue before compute(cur)
        }
        compute(cur, t, true);
        ia = ib; ib = ic; ic = in_;
        cur = nxt;
    }
}

// ---------------------------------------------------------------------------
extern "C" void kernel_launch(void* const* d_in, const int* in_sizes, int n_in,
                              void* d_out, int out_size)
{
    const float* x          = (const float*)d_in[0];
    const int*   input_ids  = (const int*)  d_in[1];
    const int*   multipliers= (const int*)  d_in[2];
    const float* embedding  = (const float*)d_in[3];
    const float* val_W      = (const float*)d_in[4];
    const float* val_b      = (const float*)d_in[5];
    const float* key_W      = (const float*)d_in[6];
    const float* key_b      = (const float*)d_in[7];
    const float* normq_w    = (const float*)d_in[8];
    const float* normk_w    = (const float*)d_in[9];
    const float* conv_w     = (const float*)d_in[10];
    const float* convnorm_w = (const float*)d_in[11];
    float* out = (float*)d_out;

    dim3 gp(10, 64, 4);
    precompute_kernel<<<gp, 256>>>(embedding, val_W, key_W, val_b, key_b);

    engram_main_kernel<<<Bq * CHUNKS, 128>>>(
        x, input_ids, multipliers,
        normq_w, normk_w, conv_w, convnorm_w, out);
}

// round 5
// speedup vs baseline: 2.1648x; 1.0410x over previous
#include <cuda_runtime.h>

// ---------------------------------------------------------------------------
// EngramModule fused forward.
// Stage 1: per-slot projection tables. 128x128 tile / 8x8 microtile GEMM.
// Stage 2: warp-per-(token-run, stream), software-pipelined: K/V gathers one
//          token ahead, q (DRAM stream) two tokens ahead.
// ---------------------------------------------------------------------------

#define Bq    8
#define Tq    4096
#define CHq   512
#define R_TOK 32
#define CHUNKS (Tq / R_TOK)   // 128

__device__ float g_Vtab[16384 * 128];   // 8 MB
__device__ float g_Ktab[16384 * 512];   // 32 MB

// ---------------------------------------------------------------------------
// Stage 1: 4 group-GEMMs of (4096 x 64) @ (64 x 640), fp32.
// Block = 128 rows x 128 cols, 256 threads, 8x8 microtile, k-chunks of 16.
// Column tile 0 -> val_W (exactly 128 rows); tiles 1..4 -> key_W 128-row slabs.
// ---------------------------------------------------------------------------
__global__ void __launch_bounds__(256) precompute_kernel(
    const float* __restrict__ emb,      // (16384, 64)
    const float* __restrict__ valW,     // (128, 256)
    const float* __restrict__ keyW,     // (512, 256)
    const float* __restrict__ valb,     // (128)
    const float* __restrict__ keyb)     // (512)
{
    __shared__ float As[16][132];
    __shared__ float Bs[16][132];

    const int tid  = threadIdx.x;
    const int nblk = blockIdx.x;   // 0..4  (col tile)
    const int mblk = blockIdx.y;   // 0..31 (row tile within group)
    const int g    = blockIdx.z;   // 0..3

    const int row0 = (tid >> 4) << 3;
    const int col0 = (tid & 15) << 3;

    float acc[8][8];
#pragma unroll
    for (int i = 0; i < 8; i++)
#pragma unroll
        for (int j = 0; j < 8; j++) acc[i][j] = 0.f;

    const float* abase = emb + (size_t)((g << 12) + (mblk << 7)) * 64;
    const float* bbase = ((nblk == 0) ? valW
                                      : keyW + (size_t)(nblk - 1) * 128 * 256)
                         + g * 64;

#pragma unroll
    for (int kc = 0; kc < 4; kc++) {
        // load A chunk (128 rows x 16 e) and B chunk (128 cols x 16 e),
        // stored transposed [e][row]. 2 float4 per thread per tile.
#pragma unroll
        for (int u = 0; u < 2; u++) {
            const int f   = tid + (u << 8);     // 0..511
            const int row = f >> 2;
            const int j   = (f & 3) << 2;       // e-offset within chunk
            float4 av = *(const float4*)(abase + row * 64  + kc * 16 + j);
            float4 bv = *(const float4*)(bbase + row * 256 + kc * 16 + j);
            As[j + 0][row] = av.x; As[j + 1][row] = av.y;
            As[j + 2][row] = av.z; As[j + 3][row] = av.w;
            Bs[j + 0][row] = bv.x; Bs[j + 1][row] = bv.y;
            Bs[j + 2][row] = bv.z; Bs[j + 3][row] = bv.w;
        }
        __syncthreads();
#pragma unroll
        for (int e = 0; e < 16; e++) {
            float4 a0 = *(const float4*)&As[e][row0];
            float4 a1 = *(const float4*)&As[e][row0 + 4];
            float4 b0 = *(const float4*)&Bs[e][col0];
            float4 b1 = *(const float4*)&Bs[e][col0 + 4];
            float ar[8] = {a0.x, a0.y, a0.z, a0.w, a1.x, a1.y, a1.z, a1.w};
            float br[8] = {b0.x, b0.y, b0.z, b0.w, b1.x, b1.y, b1.z, b1.w};
#pragma unroll
            for (int i = 0; i < 8; i++)
#pragma unroll
                for (int j = 0; j < 8; j++)
                    acc[i][j] += ar[i] * br[j];
        }
        __syncthreads();
    }

    const int slot0 = (g << 12) + (mblk << 7) + row0;
    if (nblk == 0) {
        float4 bia = *(const float4*)(valb + col0);
        float4 bib = *(const float4*)(valb + col0 + 4);
#pragma unroll
        for (int i = 0; i < 8; i++) {
            float* dst = g_Vtab + (size_t)(slot0 + i) * 128 + col0;
            float4 o0 = make_float4(acc[i][0] + 0.25f * bia.x,
                                    acc[i][1] + 0.25f * bia.y,
                                    acc[i][2] + 0.25f * bia.z,
                                    acc[i][3] + 0.25f * bia.w);
            float4 o1 = make_float4(acc[i][4] + 0.25f * bib.x,
                                    acc[i][5] + 0.25f * bib.y,
                                    acc[i][6] + 0.25f * bib.z,
                                    acc[i][7] + 0.25f * bib.w);
            *(float4*)(dst)     = o0;
            *(float4*)(dst + 4) = o1;
        }
    } else {
        const int kcol0 = (nblk - 1) * 128 + col0;
        float4 bia = *(const float4*)(keyb + kcol0);
        float4 bib = *(const float4*)(keyb + kcol0 + 4);
#pragma unroll
        for (int i = 0; i < 8; i++) {
            float* dst = g_Ktab + (size_t)(slot0 + i) * 512 + kcol0;
            float4 o0 = make_float4(acc[i][0] + 0.25f * bia.x,
                                    acc[i][1] + 0.25f * bia.y,
                                    acc[i][2] + 0.25f * bia.z,
                                    acc[i][3] + 0.25f * bia.w);
            float4 o1 = make_float4(acc[i][4] + 0.25f * bib.x,
                                    acc[i][5] + 0.25f * bib.y,
                                    acc[i][6] + 0.25f * bib.z,
                                    acc[i][7] + 0.25f * bib.w);
            *(float4*)(dst)     = o0;
            *(float4*)(dst + 4) = o1;
        }
    }
}

// ---------------------------------------------------------------------------
// Stage 2 main kernel. Block = 128 threads = 4 stream-warps of one chunk.
// K/V gathers pipelined 1 token ahead; q pipelined 2 tokens ahead.
// ---------------------------------------------------------------------------
struct Tok {
    float4 k0, k1, k2, k3;
    float4 v0, v1, v2, v3;
    float4 q;
};

__global__ void __launch_bounds__(128, 4) engram_main_kernel(
    const float* __restrict__ x,        // (B,T,4,128)
    const int*   __restrict__ ids,      // (B,T)
    const int*   __restrict__ mult,     // (2,2,3)
    const float* __restrict__ wq,       // (4,128)
    const float* __restrict__ wk,       // (4,128)
    const float* __restrict__ convw,    // (512,4)
    const float* __restrict__ convn,    // (4,128)
    float*       __restrict__ out)      // (B,T,4,128)
{
    const int stream = threadIdx.x >> 5;
    const int lane   = threadIdx.x & 31;
    const int b      = blockIdx.x >> 7;
    const int chunk  = blockIdx.x & 127;
    const int t0     = chunk * R_TOK;

    const int c = stream * 128 + lane * 4;
    const int d = lane * 4;

    const float4 wq4  = *(const float4*)(wq + c);
    const float4 wk4  = *(const float4*)(wk + c);
    const float4 wqk4 = make_float4(wq4.x * wk4.x, wq4.y * wk4.y,
                                    wq4.z * wk4.z, wq4.w * wk4.w);
    const float4 cvn4 = *(const float4*)(convn + c);
    const float4 cwA  = *(const float4*)(convw + (c + 0) * 4);
    const float4 cwB  = *(const float4*)(convw + (c + 1) * 4);
    const float4 cwC  = *(const float4*)(convw + (c + 2) * 4);
    const float4 cwD  = *(const float4*)(convw + (c + 3) * 4);

    const int m00 = mult[0],  m01 = mult[1];
    const int m10 = mult[3],  m11 = mult[4];
    const int m20 = mult[6],  m21 = mult[7],  m22 = mult[8];
    const int m30 = mult[9],  m31 = mult[10], m32 = mult[11];

    const float inv128     = 0.0078125f;
    const float eps        = 1.1920929e-7f;
    const float invsqrt128 = 0.08838834764831845f;

    const int    idBase = b * Tq;
    const float* xBase  = x   + (size_t)idBase * CHq + c;
    float*       oBase  = out + (size_t)idBase * CHq + c;

    float4 h1 = make_float4(0.f, 0.f, 0.f, 0.f);
    float4 h2 = h1;
    float4 h3 = h1;

    auto gatherKV = [&](Tok& T, int ia, int ib, int ic) {
        const int h0i = (((ib * m00) ^ (ic * m01)) & 4095);
        const int h1i = (((ib * m10) ^ (ic * m11)) & 4095) + 4096;
        const int h2i = (((ia * m20) ^ (ib * m21) ^ (ic * m22)) & 4095) + 8192;
        const int h3i = (((ia * m30) ^ (ib * m31) ^ (ic * m32)) & 4095) + 12288;
        T.k0 = __ldg((const float4*)(g_Ktab + (size_t)h0i * 512 + c));
        T.k1 = __ldg((const float4*)(g_Ktab + (size_t)h1i * 512 + c));
        T.k2 = __ldg((const float4*)(g_Ktab + (size_t)h2i * 512 + c));
        T.k3 = __ldg((const float4*)(g_Ktab + (size_t)h3i * 512 + c));
        T.v0 = __ldg((const float4*)(g_Vtab + (size_t)h0i * 128 + d));
        T.v1 = __ldg((const float4*)(g_Vtab + (size_t)h1i * 128 + d));
        T.v2 = __ldg((const float4*)(g_Vtab + (size_t)h2i * 128 + d));
        T.v3 = __ldg((const float4*)(g_Vtab + (size_t)h3i * 128 + d));
    };

    auto compute = [&](const Tok& T, int t, bool store) {
        float4 kr, vb;
        kr.x = (T.k0.x + T.k1.x) + (T.k2.x + T.k3.x);
        kr.y = (T.k0.y + T.k1.y) + (T.k2.y + T.k3.y);
        kr.z = (T.k0.z + T.k1.z) + (T.k2.z + T.k3.z);
        kr.w = (T.k0.w + T.k1.w) + (T.k2.w + T.k3.w);
        vb.x = (T.v0.x + T.v1.x) + (T.v2.x + T.v3.x);
        vb.y = (T.v0.y + T.v1.y) + (T.v2.y + T.v3.y);
        vb.z = (T.v0.z + T.v1.z) + (T.v2.z + T.v3.z);
        vb.w = (T.v0.w + T.v1.w) + (T.v2.w + T.v3.w);

        float p0 = T.q.x * T.q.x + T.q.y * T.q.y + T.q.z * T.q.z + T.q.w * T.q.w;
        float p1 = kr.x * kr.x + kr.y * kr.y + kr.z * kr.z + kr.w * kr.w;
        float p2 = T.q.x * kr.x * wqk4.x + T.q.y * kr.y * wqk4.y
                 + T.q.z * kr.z * wqk4.z + T.q.w * kr.w * wqk4.w;
        float p3 = vb.x * vb.x + vb.y * vb.y + vb.z * vb.z + vb.w * vb.w;

        const bool lo = (lane < 16);
        float ea = __shfl_xor_sync(0xffffffffu, p0, 16);
        float eb = __shfl_xor_sync(0xffffffffu, p2, 16);
        float aa = lo ? (p0 + ea) : (p2 + eb);
        float ec = __shfl_xor_sync(0xffffffffu, p1, 16);
        float ed = __shfl_xor_sync(0xffffffffu, p3, 16);
        float bb = lo ? (p1 + ec) : (p3 + ed);
#pragma unroll
        for (int off = 8; off; off >>= 1) {
            aa += __shfl_xor_sync(0xffffffffu, aa, off);
            bb += __shfl_xor_sync(0xffffffffu, bb, off);
        }
        const float a2 = __shfl_xor_sync(0xffffffffu, aa, 16);
        const float b2 = __shfl_xor_sync(0xffffffffu, bb, 16);
        const float sq  = lo ? aa : a2;
        const float sk  = lo ? bb : b2;
        const float sqk = lo ? a2 : aa;
        const float svb = lo ? b2 : bb;

        const float rsq   = rsqrtf(sq * inv128 + eps);
        const float rsk   = rsqrtf(sk * inv128 + eps);
        const float score = sqk * rsq * rsk * invsqrt128;
        const float gate  = __fdividef(1.f, 1.f + __expf(-score));
        const float rr    = rsqrtf(gate * gate * svb * inv128 + eps) * gate;

        float4 xn;
        xn.x = vb.x * rr * cvn4.x;  xn.y = vb.y * rr * cvn4.y;
        xn.z = vb.z * rr * cvn4.z;  xn.w = vb.w * rr * cvn4.w;

        if (store) {
            float4 y;
            y.x = cwA.x * h3.x + cwA.y * h2.x + cwA.z * h1.x + cwA.w * xn.x;
            y.y = cwB.x * h3.y + cwB.y * h2.y + cwB.z * h1.y + cwB.w * xn.y;
            y.z = cwC.x * h3.z + cwC.y * h2.z + cwC.z * h1.z + cwC.w * xn.z;
            y.w = cwD.x * h3.w + cwD.y * h2.w + cwD.z * h1.w + cwD.w * xn.w;
            y.x = __fdividef(y.x, 1.f + __expf(-y.x));
            y.y = __fdividef(y.y, 1.f + __expf(-y.y));
            y.z = __fdividef(y.z, 1.f + __expf(-y.z));
            y.w = __fdividef(y.w, 1.f + __expf(-y.w));
            float4 o;
            o.x = vb.x * gate + y.x;  o.y = vb.y * gate + y.y;
            o.z = vb.z * gate + y.z;  o.w = vb.w * gate + y.w;
            *(float4*)(oBase + (size_t)t * CHq) = o;
        }
        h3 = h2; h2 = h1; h1 = xn;
    };

    int ia = (t0 - 5 >= 0) ? __ldg(ids + idBase + t0 - 5) : 0;
    int ib = (t0 - 4 >= 0) ? __ldg(ids + idBase + t0 - 4) : 0;

    // ---- halo prologue: tokens t0-3 .. t0-1 (no store, unpipelined) ----
#pragma unroll
    for (int tt = -3; tt < 0; tt++) {
        const int t  = t0 + tt;
        const int ic = (t >= 0) ? __ldg(ids + idBase + t) : 0;
        if (t >= 0) {
            Tok P;
            gatherKV(P, ia, ib, ic);
            P.q = *(const float4*)(xBase + (size_t)t * CHq);
            compute(P, t, false);
        }
        ia = ib; ib = ic;
    }

    // ---- pipelined main loop ----
    int ic = __ldg(ids + idBase + t0);
    Tok cur;
    gatherKV(cur, ia, ib, ic);
    cur.q = *(const float4*)(xBase + (size_t)t0 * CHq);
    float4 qn = *(const float4*)(xBase + (size_t)(t0 + 1) * CHq);   // q(t0+1)

    for (int tt = 0; tt < R_TOK; tt++) {
        const int t = t0 + tt;
        Tok nxt;
        int in_ = ic;
        if (tt + 1 < R_TOK) {
            in_ = __ldg(ids + idBase + t + 1);
            gatherKV(nxt, ib, ic, in_);
            nxt.q = qn;
        }
        float4 qn2;
        if (tt + 2 < R_TOK)
            qn2 = *(const float4*)(xBase + (size_t)(t + 2) * CHq);  // q(t+2)
        compute(cur, t, true);
        ia = ib; ib = ic; ic = in_;
        cur = nxt;
        qn  = qn2;
    }
}

// ---------------------------------------------------------------------------
extern "C" void kernel_launch(void* const* d_in, const int* in_sizes, int n_in,
                              void* d_out, int out_size)
{
    const float* x          = (const float*)d_in[0];
    const int*   input_ids  = (const int*)  d_in[1];
    const int*   multipliers= (const int*)  d_in[2];
    const float* embedding  = (const float*)d_in[3];
    const float* val_W      = (const float*)d_in[4];
    const float* val_b      = (const float*)d_in[5];
    const float* key_W      = (const float*)d_in[6];
    const float* key_b      = (const float*)d_in[7];
    const float* normq_w    = (const float*)d_in[8];
    const float* normk_w    = (const float*)d_in[9];
    const float* conv_w     = (const float*)d_in[10];
    const float* convnorm_w = (const float*)d_in[11];
    float* out = (float*)d_out;

    dim3 gp(5, 32, 4);
    precompute_kernel<<<gp, 256>>>(embedding, val_W, key_W, val_b, key_b);

    engram_main_kernel<<<Bq * CHUNKS, 128>>>(
        x, input_ids, multipliers,
        normq_w, normk_w, conv_w, convnorm_w, out);
}